// round 7
// baseline (speedup 1.0000x reference)
#include <cuda_runtime.h>

// Geometry (fixed: importanceMap [32, 1024, 1024] fp32)
#define NBATCH            32
#define ELEM_PER_BATCH    (1 << 20)
#define V4_PER_BATCH      (1 << 18)                   // float4 per batch
#define NBLK              1024
#define THREADS           128
#define CHUNK_V4          1024                        // 16 KB chunk
#define CHUNKS_PER_BATCH  (V4_PER_BATCH / CHUNK_V4)   // 256
#define TOTAL_CHUNKS      (NBATCH * CHUNKS_PER_BATCH) // 8192
#define V4_PER_THREAD     (CHUNK_V4 / THREADS)        // 8

// Deterministic scratch (no allocations). All zero-initialized; the last
// block of every launch resets the queue state back to zero, so every
// launch (correctness run, graph capture, replays, ncu passes) starts clean.
__device__ float4   g_partial[NBATCH][CHUNKS_PER_BATCH]; // {sum s, s', s''}
__device__ float    g_c[NBATCH];
__device__ unsigned g_done[NBATCH];     // stats chunks completed per batch
__device__ unsigned g_ready[NBATCH];    // c published flag (release/acquire)
__device__ unsigned g_stats_ticket;
__device__ unsigned g_out_ticket;
__device__ unsigned g_done_ctr;

__device__ __forceinline__ float rcp_fast(float x) {
    float r; asm("rcp.approx.f32 %0, %1;" : "=f"(r) : "f"(x)); return r;
}
__device__ __forceinline__ float tanh_fast(float x) {
    float r; asm("tanh.approx.f32 %0, %1;" : "=f"(r) : "f"(x)); return r;
}

// ---------------------------------------------------------------------------
__global__ void __launch_bounds__(THREADS)
fused_kernel(const float4* __restrict__ X, float4* __restrict__ O,
             float* __restrict__ c_out)
{
    const int warp = threadIdx.x >> 5;
    const int lane = threadIdx.x & 31;

    __shared__ float    sh[THREADS / 32][3];
    __shared__ unsigned s_t;
    __shared__ int      s_last;
    __shared__ float    s_c;

    // ================= Phase 1: stats over dynamic 16 KB chunks ============
    for (;;) {
        if (threadIdx.x == 0) s_t = atomicAdd(&g_stats_ticket, 1u);
        __syncthreads();
        const unsigned t = s_t;
        if (t >= TOTAL_CHUNKS) break;
        const int batch = t >> 8;            // t / CHUNKS_PER_BATCH
        const int ck    = t & (CHUNKS_PER_BATCH - 1);
        const float4* __restrict__ base =
            X + (size_t)batch * V4_PER_BATCH + (size_t)ck * CHUNK_V4;

        // precise exp + rcp: these sums determine c (~5e-6 abs budget)
        float a0 = 0.f, a1 = 0.f, a2 = 0.f;
        #pragma unroll
        for (int k = 0; k < V4_PER_THREAD; k++) {
            float4 v = base[k * THREADS + threadIdx.x];
            float xs[4] = {v.x, v.y, v.z, v.w};
            #pragma unroll
            for (int j = 0; j < 4; j++) {
                float e = __expf(-xs[j]);
                float s = rcp_fast(1.0f + e);
                float u = __fmaf_rn(-s, s, s);          // s(1-s)
                float tt = __fmaf_rn(-2.0f, s, 1.0f);   // 1-2s
                a0 += s;
                a1 += u;
                a2 = __fmaf_rn(u, tt, a2);
            }
        }
        #pragma unroll
        for (int off = 16; off; off >>= 1) {
            a0 += __shfl_xor_sync(0xFFFFFFFFu, a0, off);
            a1 += __shfl_xor_sync(0xFFFFFFFFu, a1, off);
            a2 += __shfl_xor_sync(0xFFFFFFFFu, a2, off);
        }
        if (lane == 0) { sh[warp][0] = a0; sh[warp][1] = a1; sh[warp][2] = a2; }
        __syncthreads();
        if (threadIdx.x == 0) {
            float t0 = 0.f, t1 = 0.f, t2 = 0.f;
            #pragma unroll
            for (int w = 0; w < THREADS / 32; w++) {
                t0 += sh[w][0]; t1 += sh[w][1]; t2 += sh[w][2];
            }
            g_partial[batch][ck] = make_float4(t0, t1, t2, 0.f);
            __threadfence();                 // publish partial before counting
            unsigned old = atomicAdd(&g_done[batch], 1u);
            s_last = (old == CHUNKS_PER_BATCH - 1);
        }
        __syncthreads();

        // This block completed the batch: solve c once (fixed-order sum over
        // the 256 chunk partials -> deterministic result regardless of which
        // block executes it), publish with release.
        if (s_last && threadIdx.x < 32) {
            __threadfence();                 // acquire: see all partials
            float s0 = 0.f, s1 = 0.f, s2 = 0.f;
            #pragma unroll
            for (int j = 0; j < CHUNKS_PER_BATCH / 32; j++) {
                float4 p = __ldcg(&g_partial[batch][lane + 32 * j]);
                s0 += p.x; s1 += p.y; s2 += p.z;
            }
            #pragma unroll
            for (int off = 16; off; off >>= 1) {
                s0 += __shfl_xor_sync(0xFFFFFFFFu, s0, off);
                s1 += __shfl_xor_sync(0xFFFFFFFFu, s1, off);
                s2 += __shfl_xor_sync(0xFFFFFFFFu, s2, off);
            }
            if (lane == 0) {
                const double invN = 1.0 / (double)ELEM_PER_BATCH;
                double m0 = (double)s0 * invN - 0.5;   // f(0) - target
                double m1 = (double)s1 * invN;         // f'(0)
                double m2 = 0.5 * (double)s2 * invN;   // f''(0)/2
                double c = 0.0;
                #pragma unroll
                for (int it = 0; it < 3; it++) {
                    double g  = m0 + c * (m1 + c * m2);
                    double gp = m1 + 2.0 * m2 * c;
                    c -= g / gp;
                }
                if (c >  20.0) c =  20.0;
                if (c < -20.0) c = -20.0;
                float cf = (float)c;
                g_c[batch] = cf;
                if (c_out) c_out[batch] = cf;
                asm volatile("st.release.gpu.global.u32 [%0], %1;"
                             :: "l"(&g_ready[batch]), "r"(1u) : "memory");
            }
        }
        __syncthreads();                     // sh reusable next chunk
    }

    // ================= Phase 2: out over dynamic chunks, DESCENDING ========
    // Descending order reads the most-recently-touched X first (L2 LRU-hot).
    for (;;) {
        if (threadIdx.x == 0) s_t = atomicAdd(&g_out_ticket, 1u);
        __syncthreads();
        const unsigned t = s_t;
        if (t >= TOTAL_CHUNKS) break;
        const unsigned oc = TOTAL_CHUNKS - 1u - t;
        const int batch = oc >> 8;
        const int ck    = oc & (CHUNKS_PER_BATCH - 1);

        if (threadIdx.x == 0) {
            // Nearly always already satisfied: every stats chunk was claimed
            // by a resident block before any block reached this phase.
            for (;;) {
                unsigned v;
                asm volatile("ld.acquire.gpu.global.u32 %0, [%1];"
                             : "=r"(v) : "l"(&g_ready[batch]) : "memory");
                if (v) break;
                __nanosleep(40);
            }
            s_c = g_c[batch];
        }
        __syncthreads();
        const float halfc = 0.5f * s_c;

        const size_t off = (size_t)batch * V4_PER_BATCH + (size_t)ck * CHUNK_V4;
        const float4* __restrict__ base  = X + off;
        float4* __restrict__       obase = O + off;

        #pragma unroll
        for (int k = 0; k < V4_PER_THREAD; k++) {
            const int i = k * THREADS + threadIdx.x;
            float4 v = __ldcs(&base[i]);     // L2-hot; last use -> evict-first
            float4 r;
            r.x = __fmaf_rn(0.5f, tanh_fast(__fmaf_rn(0.5f, v.x, halfc)), 0.5f);
            r.y = __fmaf_rn(0.5f, tanh_fast(__fmaf_rn(0.5f, v.y, halfc)), 0.5f);
            r.z = __fmaf_rn(0.5f, tanh_fast(__fmaf_rn(0.5f, v.z, halfc)), 0.5f);
            r.w = __fmaf_rn(0.5f, tanh_fast(__fmaf_rn(0.5f, v.w, halfc)), 0.5f);
            __stcs(&obase[i], r);            // evict-first store
        }
        __syncthreads();                     // s_c reusable next chunk
    }

    // ================= Self-reset so every launch starts clean =============
    if (threadIdx.x == 0) {
        unsigned d = atomicAdd(&g_done_ctr, 1u);
        if (d == NBLK - 1) {                 // last block across the launch
            g_stats_ticket = 0;
            g_out_ticket   = 0;
            #pragma unroll
            for (int i = 0; i < NBATCH; i++) { g_done[i] = 0; g_ready[i] = 0; }
            g_done_ctr = 0;
            __threadfence();
        }
    }
}

// ---------------------------------------------------------------------------
extern "C" void kernel_launch(void* const* d_in, const int* in_sizes, int n_in,
                              void* d_out, int out_size)
{
    const float* X = (const float*)d_in[0];
    float* out = (float*)d_out;

    const long long map_elems = (long long)NBATCH * ELEM_PER_BATCH;
    float* c_out = ((long long)out_size > map_elems) ? (out + map_elems) : nullptr;

    fused_kernel<<<NBLK, THREADS>>>((const float4*)X, (float4*)out, c_out);
}

// round 9
// speedup vs baseline: 1.1504x; 1.1504x over previous
#include <cuda_runtime.h>

// Geometry (fixed: importanceMap [32, 1024, 1024] fp32)
#define NBATCH             32
#define ELEM_PER_BATCH     (1 << 20)
#define V4_PER_BATCH       (1 << 18)                 // float4 per batch

// stats: 4096 blocks x 128 threads, 16 float4/thread
#define S_BLOCKS           4096
#define S_THREADS          128
#define S_CHUNKS_PER_BATCH 128                       // S_BLOCKS / NBATCH
#define S_V4_PER_CHUNK     (V4_PER_BATCH / S_CHUNKS_PER_BATCH) // 2048
#define S_ITERS            (S_V4_PER_CHUNK / S_THREADS)         // 16

// out: 2048 blocks x 256 threads, 16 float4/thread
#define O_BLOCKS           2048
#define O_THREADS          256
#define O_V4_PER_BLOCK     (V4_PER_BATCH * NBATCH / O_BLOCKS)   // 4096
#define O_ITERS            (O_V4_PER_BLOCK / O_THREADS)         // 16

// Deterministic scratch (no allocations). Partials: {sum t, sum t^2},
// t = tanh(x/2):  sum_s = (sum_t + N)/2,  sum_s(1-s) = (N - sum_t2)/4.
__device__ float2 g_partial[NBATCH][S_CHUNKS_PER_BATCH];
__device__ float  g_c[NBATCH];

__device__ __forceinline__ float tanh_fast(float x) {
    float r; asm("tanh.approx.f32 %0, %1;" : "=f"(r) : "f"(x)); return r;
}

// ---------------------------------------------------------------------------
// Kernel 1: per-chunk sums of t and t^2 (t = tanh(x/2)). 4 instr + 1 MUFU
// per element -> memory-bound. No barriers, huge grid, full occupancy.
// tanh.approx precision is sufficient for c: R2 vs R4 showed its per-element
// error is ~1e-5-level; bias shifts c by ~3.5x that -> ~3e-5 (budget 1.6e-3).
// ---------------------------------------------------------------------------
__global__ void __launch_bounds__(S_THREADS)
stats_kernel(const float4* __restrict__ X)
{
    const int batch = blockIdx.x >> 7;               // / S_CHUNKS_PER_BATCH
    const int chunk = blockIdx.x & (S_CHUNKS_PER_BATCH - 1);
    const float4* __restrict__ p =
        X + (size_t)batch * V4_PER_BATCH + (size_t)chunk * S_V4_PER_CHUNK;

    float at = 0.f, at2 = 0.f;
    #pragma unroll
    for (int k = 0; k < S_ITERS; k++) {
        float4 v = __ldcg(&p[k * S_THREADS + threadIdx.x]);
        float t0 = tanh_fast(0.5f * v.x);
        float t1 = tanh_fast(0.5f * v.y);
        float t2 = tanh_fast(0.5f * v.z);
        float t3 = tanh_fast(0.5f * v.w);
        at += t0;  at2 = __fmaf_rn(t0, t0, at2);
        at += t1;  at2 = __fmaf_rn(t1, t1, at2);
        at += t2;  at2 = __fmaf_rn(t2, t2, at2);
        at += t3;  at2 = __fmaf_rn(t3, t3, at2);
    }

    // fixed-order reduction -> deterministic
    #pragma unroll
    for (int off = 16; off; off >>= 1) {
        at  += __shfl_xor_sync(0xFFFFFFFFu, at,  off);
        at2 += __shfl_xor_sync(0xFFFFFFFFu, at2, off);
    }
    __shared__ float sh[S_THREADS / 32][2];
    const int warp = threadIdx.x >> 5, lane = threadIdx.x & 31;
    if (lane == 0) { sh[warp][0] = at; sh[warp][1] = at2; }
    __syncthreads();
    if (threadIdx.x == 0) {
        float t0 = 0.f, t1 = 0.f;
        #pragma unroll
        for (int w = 0; w < S_THREADS / 32; w++) { t0 += sh[w][0]; t1 += sh[w][1]; }
        g_partial[batch][chunk] = make_float2(t0, t1);
    }
}

// ---------------------------------------------------------------------------
// Kernel 2: solve c per batch. warp w <-> batch w; fixed-order reduction of
// the 128 chunk partials, then closed-form from the linear model:
//   f(c)-0.5 ~= (sum_t)/(2N) + c*(N - sum_t2)/(4N)  =>  c = -2*sum_t/(N-sum_t2)
// (quadratic term contributes ~1e-8 to c for this data; dropped.)
// ---------------------------------------------------------------------------
__global__ void solve_kernel(float* __restrict__ c_out)
{
    const int batch = threadIdx.x >> 5;
    const int lane  = threadIdx.x & 31;

    float2 p0 = g_partial[batch][lane];
    float2 p1 = g_partial[batch][lane + 32];
    float2 p2 = g_partial[batch][lane + 64];
    float2 p3 = g_partial[batch][lane + 96];
    float st  = (p0.x + p1.x) + (p2.x + p3.x);
    float st2 = (p0.y + p1.y) + (p2.y + p3.y);
    #pragma unroll
    for (int off = 16; off; off >>= 1) {
        st  += __shfl_xor_sync(0xFFFFFFFFu, st,  off);
        st2 += __shfl_xor_sync(0xFFFFFFFFu, st2, off);
    }
    if (lane == 0) {
        double c = -2.0 * (double)st / ((double)ELEM_PER_BATCH - (double)st2);
        if (c >  20.0) c =  20.0;
        if (c < -20.0) c = -20.0;
        float cf = (float)c;
        g_c[batch] = cf;
        if (c_out) c_out[batch] = cf;
    }
}

// ---------------------------------------------------------------------------
// Kernel 3: out = sigmoid(x + c) = 0.5*tanh((x+c)/2) + 0.5.
// X was just streamed through L2 by stats (126 MB capacity vs 128 MB data):
// reads are L2-served. Stores use WRITE-THROUGH (__stwt) so output lines do
// not accumulate dirty in L2 and evict X (the R2 failure mode with .cs).
// ---------------------------------------------------------------------------
__global__ void __launch_bounds__(O_THREADS)
out_kernel(const float4* __restrict__ X, float4* __restrict__ O)
{
    const int  base  = blockIdx.x * O_V4_PER_BLOCK;
    const int  batch = base >> 18;                    // 2^18 float4 per batch

    __shared__ float sc;
    if (threadIdx.x == 0) sc = __ldcg(&g_c[batch]);
    __syncthreads();
    const float halfc = 0.5f * sc;

    #pragma unroll
    for (int k = 0; k < O_ITERS; k++) {
        const int i = base + k * O_THREADS + threadIdx.x;
        float4 v = __ldcg(&X[i]);                     // L2-hot from stats pass
        float4 r;
        r.x = __fmaf_rn(0.5f, tanh_fast(__fmaf_rn(0.5f, v.x, halfc)), 0.5f);
        r.y = __fmaf_rn(0.5f, tanh_fast(__fmaf_rn(0.5f, v.y, halfc)), 0.5f);
        r.z = __fmaf_rn(0.5f, tanh_fast(__fmaf_rn(0.5f, v.z, halfc)), 0.5f);
        r.w = __fmaf_rn(0.5f, tanh_fast(__fmaf_rn(0.5f, v.w, halfc)), 0.5f);
        __stwt(&O[i], r);                             // write-through: no dirty
    }                                                 // lines displacing X
}

// ---------------------------------------------------------------------------
extern "C" void kernel_launch(void* const* d_in, const int* in_sizes, int n_in,
                              void* d_out, int out_size)
{
    const float* X = (const float*)d_in[0];
    float* out = (float*)d_out;

    const long long map_elems = (long long)NBATCH * ELEM_PER_BATCH;
    float* c_out = ((long long)out_size > map_elems) ? (out + map_elems) : nullptr;

    stats_kernel<<<S_BLOCKS, S_THREADS>>>((const float4*)X);
    solve_kernel<<<1, NBATCH * 32>>>(c_out);
    out_kernel<<<O_BLOCKS, O_THREADS>>>((const float4*)X, (float4*)out);
}